// round 10
// baseline (speedup 1.0000x reference)
#include <cuda_runtime.h>
#include <math.h>
#include <stdint.h>

#define NB 32
#define NHQ 32
#define NHKV 8
#define NG 4
#define DHD 128
#define HID 4096
#define PAST 4096
#define TTOT 4097
#define NSPLIT 32
#define CHUNK (PAST / NSPLIT)      // 128
#define KTILE 32
#define NT (CHUNK / KTILE)         // 4
#define SPLITK 8
#define KS (HID / SPLITK)          // 512
#define ATT_SCALE 0.08838834764831845f
#define OQ 4096
#define OKV 1024
#define OQKV 6144

#define KPAD 132
#define TILE_KF (KTILE * KPAD)
#define TILE_VF (KTILE * DHD)
#define ATTN_SMEM_F (NG * DHD + CHUNK + 2 * TILE_KF + 2 * TILE_VF)
#define ATTN_SMEM_BYTES (ATTN_SMEM_F * 4)

// ---- mma.sync tf32 GEMM: block = 32 b x 64 o, stage = 64 k, dyn smem ----
#define GOB 64
#define GKS 64
#define GNSTG (KS / GKS)           // 8 stages
#define GSTR 68                    // row stride (floats); 68%32==4 -> conflict-free
#define XS_F (NB * GSTR)           // 2176 floats per x-stage
#define WS_F (GOB * GSTR)          // 4352 floats per w-stage
#define GEMM_SMEM_B ((2 * XS_F + 2 * WS_F) * 4)   // 52224 B

// ---------------- scratch ----------------------------------------------------
static __device__ float g_qkv_part[SPLITK][NB * OQKV];
static __device__ float g_qkv[NB * OQKV];
static __device__ float g_out_part[SPLITK][NB * HID];
static __device__ float g_pm[NB * NHKV * NG * NSPLIT];
static __device__ float g_pl[NB * NHKV * NG * NSPLIT];
static __device__ float g_pacc[NB * NHKV * NG * NSPLIT * DHD];
static __device__ float g_ctx[NB * NHQ * DHD];
static __device__ int   g_dummy_sink;

typedef unsigned long long u64;

__device__ __forceinline__ u64 fma2(u64 a, u64 b, u64 c) {
    u64 d;
    asm("fma.rn.f32x2 %0, %1, %2, %3;" : "=l"(d) : "l"(a), "l"(b), "l"(c));
    return d;
}
__device__ __forceinline__ u64 dup2(float x) {
    u64 d; unsigned xi = __float_as_uint(x);
    asm("mov.b64 %0, {%1, %1};" : "=l"(d) : "r"(xi));
    return d;
}
__device__ __forceinline__ float2 un2(u64 v) {
    float2 r;
    asm("mov.b64 {%0, %1}, %2;" : "=f"(r.x), "=f"(r.y) : "l"(v));
    return r;
}
__device__ __forceinline__ float warp_max(float v) {
    #pragma unroll
    for (int o = 16; o > 0; o >>= 1) v = fmaxf(v, __shfl_xor_sync(0xffffffffu, v, o));
    return v;
}
__device__ __forceinline__ float warp_sum(float v) {
    #pragma unroll
    for (int o = 16; o > 0; o >>= 1) v += __shfl_xor_sync(0xffffffffu, v, o);
    return v;
}
__device__ __forceinline__ void cp_async16(uint32_t saddr, const void* gptr) {
    asm volatile("cp.async.cg.shared.global [%0], [%1], 16;" :: "r"(saddr), "l"(gptr));
}
__device__ __forceinline__ uint32_t to_tf32(float f) {
    uint32_t u;
    asm("cvt.rna.tf32.f32 %0, %1;" : "=r"(u) : "f"(f));
    return u;
}

// ---------------- tf32 mma.sync GEMM tile (64-k stages, hoisted addresses) ---
__device__ __forceinline__ void gemm_mma_tile(
    const float* __restrict__ X, const float* __restrict__ W,
    float* __restrict__ Y, int ldY, int ocol0, int k0)
{
    extern __shared__ __align__(16) float gsm[];
    float* xsb[2] = { gsm, gsm + XS_F };
    float* wsb[2] = { gsm + 2 * XS_F, gsm + 2 * XS_F + WS_F };
    uint32_t smb = (uint32_t)__cvta_generic_to_shared(gsm);
    uint32_t xsa[2] = { smb, smb + XS_F * 4 };
    uint32_t wsa[2] = { smb + 2 * XS_F * 4, smb + (2 * XS_F + WS_F) * 4 };

    int t = threadIdx.x, warp = t >> 5, lane = t & 31;
    int qr = lane >> 2, qc = lane & 3;

    // hoisted per-iteration addresses (stage adds only kk)
    const float* xg[4]; uint32_t xo[4];
    const float* wg[8]; uint32_t wo[8];
    #pragma unroll
    for (int it = 0; it < 4; it++) {
        int idx = it * 128 + t;
        int row = idx >> 4, c4 = idx & 15;
        xg[it] = X + (size_t)row * HID + k0 + c4 * 4;
        xo[it] = (uint32_t)(row * GSTR + c4 * 4) * 4;
    }
    #pragma unroll
    for (int it = 0; it < 8; it++) {
        int idx = it * 128 + t;
        int row = idx >> 4, c4 = idx & 15;
        wg[it] = W + (size_t)row * HID + k0 + c4 * 4;
        wo[it] = (uint32_t)(row * GSTR + c4 * 4) * 4;
    }

    float c[2][2][4];
    #pragma unroll
    for (int mt = 0; mt < 2; mt++)
        #pragma unroll
        for (int nt = 0; nt < 2; nt++)
            #pragma unroll
            for (int i = 0; i < 4; i++) c[mt][nt][i] = 0.f;

    #define GLOAD(s_) do {                                                        \
        int buf = (s_) & 1; int kk = (s_) * GKS;                                  \
        _Pragma("unroll")                                                         \
        for (int it = 0; it < 4; it++) cp_async16(xsa[buf] + xo[it], xg[it] + kk);\
        _Pragma("unroll")                                                         \
        for (int it = 0; it < 8; it++) cp_async16(wsa[buf] + wo[it], wg[it] + kk);\
        asm volatile("cp.async.commit_group;" ::: "memory");                      \
    } while (0)

    GLOAD(0);
    for (int s = 0; s < GNSTG; s++) {
        if (s + 1 < GNSTG) {
            GLOAD(s + 1);
            asm volatile("cp.async.wait_group 1;" ::: "memory");
        } else {
            asm volatile("cp.async.wait_group 0;" ::: "memory");
        }
        __syncthreads();
        const float* xb = xsb[s & 1];
        const float* wb = wsb[s & 1];
        #pragma unroll
        for (int ks = 0; ks < 8; ks++) {
            int kc = ks * 8;
            uint32_t A[2][4], B[2][2];
            #pragma unroll
            for (int mt = 0; mt < 2; mt++) {
                int r0 = mt * 16 + qr;
                A[mt][0] = to_tf32(xb[(r0)     * GSTR + kc + qc]);
                A[mt][1] = to_tf32(xb[(r0 + 8) * GSTR + kc + qc]);
                A[mt][2] = to_tf32(xb[(r0)     * GSTR + kc + qc + 4]);
                A[mt][3] = to_tf32(xb[(r0 + 8) * GSTR + kc + qc + 4]);
            }
            #pragma unroll
            for (int nt = 0; nt < 2; nt++) {
                int o = warp * 16 + nt * 8 + qr;
                B[nt][0] = to_tf32(wb[o * GSTR + kc + qc]);
                B[nt][1] = to_tf32(wb[o * GSTR + kc + qc + 4]);
            }
            #pragma unroll
            for (int mt = 0; mt < 2; mt++)
                #pragma unroll
                for (int nt = 0; nt < 2; nt++)
                    asm volatile(
                        "mma.sync.aligned.m16n8k8.row.col.f32.tf32.tf32.f32 "
                        "{%0,%1,%2,%3}, {%4,%5,%6,%7}, {%8,%9}, {%0,%1,%2,%3};"
                        : "+f"(c[mt][nt][0]), "+f"(c[mt][nt][1]),
                          "+f"(c[mt][nt][2]), "+f"(c[mt][nt][3])
                        : "r"(A[mt][0]), "r"(A[mt][1]), "r"(A[mt][2]), "r"(A[mt][3]),
                          "r"(B[nt][0]), "r"(B[nt][1]));
        }
        __syncthreads();
    }
    #undef GLOAD

    #pragma unroll
    for (int mt = 0; mt < 2; mt++)
        #pragma unroll
        for (int nt = 0; nt < 2; nt++) {
            int o = ocol0 + warp * 16 + nt * 8 + qc * 2;
            int b0 = mt * 16 + qr;
            *(float2*)(&Y[(size_t)b0 * ldY + o])       = make_float2(c[mt][nt][0], c[mt][nt][1]);
            *(float2*)(&Y[(size_t)(b0 + 8) * ldY + o]) = make_float2(c[mt][nt][2], c[mt][nt][3]);
        }
}

__global__ __launch_bounds__(128) void gemm_qkv_kernel(
    const float* __restrict__ X, const float* __restrict__ Wq,
    const float* __restrict__ Wk, const float* __restrict__ Wv)
{
    int o0 = blockIdx.x * GOB;
    int sp = blockIdx.y;
    const float* W;
    if (o0 < OQ)            W = Wq + (size_t)o0 * HID;
    else if (o0 < OQ + OKV) W = Wk + (size_t)(o0 - OQ) * HID;
    else                    W = Wv + (size_t)(o0 - OQ - OKV) * HID;
    gemm_mma_tile(X, W, g_qkv_part[sp], OQKV, o0, sp * KS);
}

__global__ __launch_bounds__(128) void gemm_wo_kernel(const float* __restrict__ Wo)
{
    int o0 = blockIdx.x * GOB;
    int sp = blockIdx.y;
    gemm_mma_tile(g_ctx, Wo + (size_t)o0 * HID, g_out_part[sp], HID, o0, sp * KS);
}

// -------- reduce split-K partials + RoPE (q,k) / identity (v) ----------------
__global__ __launch_bounds__(128) void reduce_rope_kernel(
    const int* __restrict__ pos, const float* __restrict__ cosc,
    const float* __restrict__ sinc)
{
    int u = blockIdx.x % 48;
    int b = blockIdx.x / 48;
    int t = threadIdx.x;
    size_t base = (size_t)b * OQKV + u * 128;
    if (u < 40) {
        if (t < 64) {
            float x1 = 0.f, x2 = 0.f;
            #pragma unroll
            for (int s = 0; s < SPLITK; s++) {
                x1 += g_qkv_part[s][base + t];
                x2 += g_qkv_part[s][base + t + 64];
            }
            int p = pos[b];
            float c = cosc[p * 64 + t], sn = sinc[p * 64 + t];
            g_qkv[base + t]      = x1 * c - x2 * sn;
            g_qkv[base + t + 64] = x2 * c + x1 * sn;
        }
    } else {
        float x = 0.f;
        #pragma unroll
        for (int s = 0; s < SPLITK; s++) x += g_qkv_part[s][base + t];
        g_qkv[base + t] = x;
    }
}

__global__ __launch_bounds__(128) void reduce_out_kernel(float* __restrict__ out)
{
    int i = blockIdx.x * 128 + threadIdx.x;
    float x = 0.f;
    #pragma unroll
    for (int s = 0; s < SPLITK; s++) x += g_out_part[s][i];
    out[i] = x;
}

// Profiling shims: gemm_qkv lands on captured launch idx 3.
__global__ void profile_shim_kernel() { if (threadIdx.x == 1024) g_dummy_sink = 1; }

// ---------------- fused flash-decode split + KV-cache copy -------------------
__global__ __launch_bounds__(128) void attn_kernel(
    const float* __restrict__ pk, const float* __restrict__ pv,
    const float* __restrict__ bias, float* __restrict__ out_k,
    float* __restrict__ out_v)
{
    extern __shared__ __align__(16) float smem[];
    float* qs = smem;
    float* sbias = smem + NG*DHD;
    float* bufK[2] = { smem + NG*DHD + CHUNK, smem + NG*DHD + CHUNK + TILE_KF };
    float* bufV[2] = { smem + NG*DHD + CHUNK + 2*TILE_KF,
                       smem + NG*DHD + CHUNK + 2*TILE_KF + TILE_VF };

    int split = blockIdx.x, h = blockIdx.y, b = blockIdx.z;
    int t = threadIdx.x, warp = t >> 5, lane = t & 31;

    const float* kbase = pk + (size_t)(b * NHKV + h) * PAST * DHD;
    const float* vbase = pv + (size_t)(b * NHKV + h) * PAST * DHD;
    float* okbase = out_k + (size_t)(b * NHKV + h) * TTOT * DHD;
    float* ovbase = out_v + (size_t)(b * NHKV + h) * TTOT * DHD;

    uint32_t sm0 = (uint32_t)__cvta_generic_to_shared(smem);
    uint32_t kOff[2] = { sm0 + (uint32_t)(NG*DHD + CHUNK)*4,
                         sm0 + (uint32_t)(NG*DHD + CHUNK + TILE_KF)*4 };
    uint32_t vOff[2] = { sm0 + (uint32_t)(NG*DHD + CHUNK + 2*TILE_KF)*4,
                         sm0 + (uint32_t)(NG*DHD + CHUNK + 2*TILE_KF + TILE_VF)*4 };

    int tstart = split * CHUNK;

    {
        #pragma unroll
        for (int it = 0; it < 8; it++) {
            int idx = it * 128 + t;
            int rr = idx >> 5, c4 = idx & 31;
            size_t go = (size_t)(tstart + rr) * DHD + c4 * 4;
            cp_async16(kOff[0] + (uint32_t)(rr * KPAD + c4 * 4) * 4, kbase + go);
            cp_async16(vOff[0] + (uint32_t)(rr * DHD  + c4 * 4) * 4, vbase + go);
        }
        asm volatile("cp.async.commit_group;" ::: "memory");
    }

    for (int i = t; i < NG * DHD; i += 128)
        qs[i] = g_qkv[(size_t)b * OQKV + (h * NG + (i >> 7)) * DHD + (i & 127)];
    sbias[t] = bias[(size_t)b * TTOT + tstart + t];

    float m = -INFINITY, l = 0.f;
    u64 a01 = 0ull, a23 = 0ull;

    for (int ti = 0; ti < NT; ti++) {
        int t0 = tstart + ti * KTILE;
        int cur = ti & 1;
        if (ti + 1 < NT) {
            int nxt = cur ^ 1;
            int t1 = t0 + KTILE;
            #pragma unroll
            for (int it = 0; it < 8; it++) {
                int idx = it * 128 + t;
                int rr = idx >> 5, c4 = idx & 31;
                size_t go = (size_t)(t1 + rr) * DHD + c4 * 4;
                cp_async16(kOff[nxt] + (uint32_t)(rr * KPAD + c4 * 4) * 4, kbase + go);
                cp_async16(vOff[nxt] + (uint32_t)(rr * DHD  + c4 * 4) * 4, vbase + go);
            }
            asm volatile("cp.async.commit_group;" ::: "memory");
            asm volatile("cp.async.wait_group 1;" ::: "memory");
        } else {
            asm volatile("cp.async.wait_group 0;" ::: "memory");
        }
        __syncthreads();

        const float* kb = bufK[cur];
        const float* vb = bufV[cur];

        if (t == 0) {
            asm volatile("fence.proxy.async.shared::cta;" ::: "memory");
            asm volatile("cp.async.bulk.global.shared::cta.bulk_group [%0], [%1], %2;"
                         :: "l"(ovbase + (size_t)t0 * DHD), "r"(vOff[cur]),
                            "r"((int)(TILE_VF * 4)) : "memory");
            asm volatile("cp.async.bulk.commit_group;" ::: "memory");
        }

        const float* qg = qs + warp * DHD;
        u64 s01 = 0ull, s23 = 0ull;
        #pragma unroll
        for (int d4 = 0; d4 < 32; d4++) {
            ulonglong2 qv = *(const ulonglong2*)(qg + d4 * 4);
            ulonglong2 kv = *(const ulonglong2*)(kb + (size_t)lane * KPAD + d4 * 4);
            s01 = fma2(qv.x, kv.x, s01);
            s23 = fma2(qv.y, kv.y, s23);
        }
        float2 sa = un2(s01), sb = un2(s23);
        float s = ((sa.x + sa.y) + (sb.x + sb.y)) * ATT_SCALE + sbias[ti * KTILE + lane];

        float mt = warp_max(s);
        float mnew = fmaxf(m, mt);
        float alpha = __expf(m - mnew);
        float p = __expf(s - mnew);
        l = l * alpha + warp_sum(p);
        m = mnew;
        u64 al2 = dup2(alpha);
        a01 = fma2(a01, al2, 0ull);
        a23 = fma2(a23, al2, 0ull);
        #pragma unroll
        for (int j = 0; j < KTILE; j++) {
            float pj = __shfl_sync(0xffffffffu, p, j);
            u64 pj2 = dup2(pj);
            ulonglong2 vv = *(const ulonglong2*)(vb + j * DHD + lane * 4);
            a01 = fma2(pj2, vv.x, a01);
            a23 = fma2(pj2, vv.y, a23);
        }

        #pragma unroll
        for (int it = 0; it < 8; it++) {
            int idx = it * 128 + t;
            int rr = idx >> 5, c4 = idx & 31;
            __stcs((float4*)(okbase + (size_t)(t0 + rr) * DHD + c4 * 4),
                   *(const float4*)(kb + rr * KPAD + c4 * 4));
        }

        if (t == 0)
            asm volatile("cp.async.bulk.wait_group.read 0;" ::: "memory");
        __syncthreads();
    }

    float2 f0 = un2(a01), f1 = un2(a23);
    float4 a = make_float4(f0.x, f0.y, f1.x, f1.y);

    if (split == NSPLIT - 1) {
        const float* kn = &g_qkv[(size_t)b * OQKV + OQ + h * DHD];
        const float* vn = &g_qkv[(size_t)b * OQKV + OQ + OKV + h * DHD];
        if (t < 32)      *(float4*)(okbase + (size_t)PAST * DHD + t * 4) = *(const float4*)(kn + t * 4);
        else if (t < 64) *(float4*)(ovbase + (size_t)PAST * DHD + (t - 32) * 4) = *(const float4*)(vn + (t - 32) * 4);
        float sp = 0.f;
        #pragma unroll
        for (int i = lane; i < DHD; i += 32) sp += qs[warp * DHD + i] * kn[i];
        sp = warp_sum(sp) * ATT_SCALE + bias[(size_t)b * TTOT + PAST];
        float mnew = fmaxf(m, sp);
        float alpha = __expf(m - mnew);
        float p = __expf(sp - mnew);
        l = l * alpha + p;
        m = mnew;
        float4 vv = *(const float4*)(vn + lane * 4);
        a.x = a.x * alpha + p * vv.x; a.y = a.y * alpha + p * vv.y;
        a.z = a.z * alpha + p * vv.z; a.w = a.w * alpha + p * vv.w;
    }

    int pidx = ((b * NHKV + h) * NG + warp) * NSPLIT + split;
    if (lane == 0) { g_pm[pidx] = m; g_pl[pidx] = l; }
    *(float4*)(&g_pacc[(size_t)pidx * DHD + lane * 4]) = a;

    if (t == 0)
        asm volatile("cp.async.bulk.wait_group 0;" ::: "memory");
}

// ---------------- combine split partials -> context --------------------------
__global__ __launch_bounds__(128) void combine_kernel()
{
    int bh = blockIdx.x;
    int b = bh / NHQ, hq = bh % NHQ;
    int h = hq / NG, g = hq % NG;
    int pbase = ((b * NHKV + h) * NG + g) * NSPLIT;
    int d = threadIdx.x;

    float M = -INFINITY;
    #pragma unroll
    for (int s = 0; s < NSPLIT; s++) M = fmaxf(M, g_pm[pbase + s]);
    float L0 = 0.f, L1 = 0.f, c0 = 0.f, c1 = 0.f;
    #pragma unroll
    for (int s = 0; s < NSPLIT; s += 2) {
        float w0 = __expf(g_pm[pbase + s]     - M);
        float w1 = __expf(g_pm[pbase + s + 1] - M);
        L0 += w0 * g_pl[pbase + s];
        L1 += w1 * g_pl[pbase + s + 1];
        c0 += w0 * g_pacc[(size_t)(pbase + s)     * DHD + d];
        c1 += w1 * g_pacc[(size_t)(pbase + s + 1) * DHD + d];
    }
    g_ctx[(size_t)bh * DHD + d] = (c0 + c1) / (L0 + L1);
}

// ---------------- launch ----------------------------------------------------
extern "C" void kernel_launch(void* const* d_in, const int* in_sizes, int n_in,
                              void* d_out, int out_size)
{
    const float* hidden = (const float*)d_in[0];
    const float* bias   = (const float*)d_in[1];
    const int*   pos    = (const int*)d_in[2];
    const float* cosc   = (const float*)d_in[3];
    const float* sinc   = (const float*)d_in[4];
    const float* pk     = (const float*)d_in[5];
    const float* pv     = (const float*)d_in[6];
    const float* Wq     = (const float*)d_in[7];
    const float* Wk     = (const float*)d_in[8];
    const float* Wv     = (const float*)d_in[9];
    const float* Wo     = (const float*)d_in[10];

    float* out = (float*)d_out;
    size_t kv_elems = (size_t)NB * NHKV * TTOT * DHD;
    float* out_k = out + (size_t)NB * HID;
    float* out_v = out_k + kv_elems;

    static bool attr_set = false;
    if (!attr_set) {
        cudaFuncSetAttribute(attn_kernel, cudaFuncAttributeMaxDynamicSharedMemorySize,
                             ATTN_SMEM_BYTES);
        cudaFuncSetAttribute(gemm_qkv_kernel, cudaFuncAttributeMaxDynamicSharedMemorySize,
                             GEMM_SMEM_B);
        cudaFuncSetAttribute(gemm_wo_kernel, cudaFuncAttributeMaxDynamicSharedMemorySize,
                             GEMM_SMEM_B);
        attr_set = true;
    }

    profile_shim_kernel<<<1, 32>>>();
    profile_shim_kernel<<<1, 32>>>();
    profile_shim_kernel<<<1, 32>>>();   // gemm_qkv lands on captured launch idx 3
    gemm_qkv_kernel<<<dim3(OQKV / GOB, SPLITK), 128, GEMM_SMEM_B>>>(hidden, Wq, Wk, Wv);
    reduce_rope_kernel<<<NB * 48, 128>>>(pos, cosc, sinc);
    attn_kernel<<<dim3(NSPLIT, NHKV, NB), 128, ATTN_SMEM_BYTES>>>(pk, pv, bias, out_k, out_v);
    combine_kernel<<<NB * NHQ, 128>>>();
    gemm_wo_kernel<<<dim3(HID / GOB, SPLITK), 128, GEMM_SMEM_B>>>(Wo);
    reduce_out_kernel<<<NB * HID / 128, 128>>>(out);
}

// round 11
// speedup vs baseline: 1.0161x; 1.0161x over previous
#include <cuda_runtime.h>
#include <math.h>
#include <stdint.h>

#define NB 32
#define NHQ 32
#define NHKV 8
#define NG 4
#define DHD 128
#define HID 4096
#define PAST 4096
#define TTOT 4097
#define NSPLIT 32
#define CHUNK (PAST / NSPLIT)      // 128
#define KTILE 32
#define NT (CHUNK / KTILE)         // 4
#define SPLITK 16
#define KS (HID / SPLITK)          // 256
#define ATT_SCALE 0.08838834764831845f
#define OQ 4096
#define OKV 1024
#define OQKV 6144

#define KPAD 132
#define TILE_KF (KTILE * KPAD)
#define TILE_VF (KTILE * DHD)
#define ATTN_SMEM_F (NG * DHD + CHUNK + 2 * TILE_KF + 2 * TILE_VF)
#define ATTN_SMEM_BYTES (ATTN_SMEM_F * 4)

// ---- mma.sync tf32 GEMM geometry: block = 32 b x 64 o, stage = 32 k ----
#define GOB 64
#define GKS 32
#define GNSTG (KS / GKS)           // 8 stages
#define XSTR 36
#define WSTR 36

// ---------------- scratch ----------------------------------------------------
static __device__ float g_qkv_part[SPLITK][NB * OQKV];
static __device__ float g_qkv[NB * OQKV];
static __device__ float g_out_part[SPLITK][NB * HID];
static __device__ float g_pm[NB * NHKV * NG * NSPLIT];
static __device__ float g_pl[NB * NHKV * NG * NSPLIT];
static __device__ float g_pacc[NB * NHKV * NG * NSPLIT * DHD];
static __device__ float g_ctx[NB * NHQ * DHD];
static __device__ int   g_dummy_sink;

typedef unsigned long long u64;

__device__ __forceinline__ u64 fma2(u64 a, u64 b, u64 c) {
    u64 d;
    asm("fma.rn.f32x2 %0, %1, %2, %3;" : "=l"(d) : "l"(a), "l"(b), "l"(c));
    return d;
}
__device__ __forceinline__ u64 dup2(float x) {
    u64 d; unsigned xi = __float_as_uint(x);
    asm("mov.b64 %0, {%1, %1};" : "=l"(d) : "r"(xi));
    return d;
}
__device__ __forceinline__ float2 un2(u64 v) {
    float2 r;
    asm("mov.b64 {%0, %1}, %2;" : "=f"(r.x), "=f"(r.y) : "l"(v));
    return r;
}
__device__ __forceinline__ float warp_max(float v) {
    #pragma unroll
    for (int o = 16; o > 0; o >>= 1) v = fmaxf(v, __shfl_xor_sync(0xffffffffu, v, o));
    return v;
}
__device__ __forceinline__ float warp_sum(float v) {
    #pragma unroll
    for (int o = 16; o > 0; o >>= 1) v += __shfl_xor_sync(0xffffffffu, v, o);
    return v;
}
__device__ __forceinline__ void cp_async16(uint32_t saddr, const void* gptr) {
    asm volatile("cp.async.cg.shared.global [%0], [%1], 16;" :: "r"(saddr), "l"(gptr));
}
__device__ __forceinline__ uint32_t to_tf32(float f) {
    uint32_t u;
    asm("cvt.rna.tf32.f32 %0, %1;" : "=r"(u) : "f"(f));
    return u;
}

// ---------------- tf32 mma.sync GEMM tile (R9 config) ------------------------
__device__ __forceinline__ void gemm_mma_tile(
    const float* __restrict__ X, const float* __restrict__ W,
    float* __restrict__ Y, int ldY, int ocol0, int k0,
    float* xs0, float* xs1, float* ws0, float* ws1)
{
    int t = threadIdx.x, warp = t >> 5, lane = t & 31;
    int qr = lane >> 2, qc = lane & 3;

    float c[2][2][4];
    #pragma unroll
    for (int mt = 0; mt < 2; mt++)
        #pragma unroll
        for (int nt = 0; nt < 2; nt++)
            #pragma unroll
            for (int i = 0; i < 4; i++) c[mt][nt][i] = 0.f;

    float* xsb[2] = { xs0, xs1 };
    float* wsb[2] = { ws0, ws1 };
    uint32_t xsa[2] = { (uint32_t)__cvta_generic_to_shared(xs0),
                        (uint32_t)__cvta_generic_to_shared(xs1) };
    uint32_t wsa[2] = { (uint32_t)__cvta_generic_to_shared(ws0),
                        (uint32_t)__cvta_generic_to_shared(ws1) };

    #define GLOAD(s_) do {                                                        \
        int buf = (s_) & 1;                                                       \
        int kk = k0 + (s_) * GKS;                                                 \
        _Pragma("unroll")                                                         \
        for (int it = 0; it < 2; it++) {                                          \
            int idx = it * 128 + t; int row = idx >> 3, c4 = idx & 7;             \
            cp_async16(xsa[buf] + (uint32_t)(row * XSTR + c4 * 4) * 4,            \
                       X + (size_t)row * HID + kk + c4 * 4);                      \
        }                                                                         \
        _Pragma("unroll")                                                         \
        for (int it = 0; it < 4; it++) {                                          \
            int idx = it * 128 + t; int row = idx >> 3, c4 = idx & 7;             \
            cp_async16(wsa[buf] + (uint32_t)(row * WSTR + c4 * 4) * 4,            \
                       W + (size_t)row * HID + kk + c4 * 4);                      \
        }                                                                         \
        asm volatile("cp.async.commit_group;" ::: "memory");                      \
    } while (0)

    GLOAD(0);
    for (int s = 0; s < GNSTG; s++) {
        if (s + 1 < GNSTG) {
            GLOAD(s + 1);
            asm volatile("cp.async.wait_group 1;" ::: "memory");
        } else {
            asm volatile("cp.async.wait_group 0;" ::: "memory");
        }
        __syncthreads();
        const float* xb = xsb[s & 1];
        const float* wb = wsb[s & 1];
        #pragma unroll
        for (int ks = 0; ks < 4; ks++) {
            int kc = ks * 8;
            uint32_t A[2][4], B[2][2];
            #pragma unroll
            for (int mt = 0; mt < 2; mt++) {
                int r0 = mt * 16 + qr;
                A[mt][0] = to_tf32(xb[(r0)     * XSTR + kc + qc]);
                A[mt][1] = to_tf32(xb[(r0 + 8) * XSTR + kc + qc]);
                A[mt][2] = to_tf32(xb[(r0)     * XSTR + kc + qc + 4]);
                A[mt][3] = to_tf32(xb[(r0 + 8) * XSTR + kc + qc + 4]);
            }
            #pragma unroll
            for (int nt = 0; nt < 2; nt++) {
                int o = warp * 16 + nt * 8 + qr;
                B[nt][0] = to_tf32(wb[o * WSTR + kc + qc]);
                B[nt][1] = to_tf32(wb[o * WSTR + kc + qc + 4]);
            }
            #pragma unroll
            for (int mt = 0; mt < 2; mt++)
                #pragma unroll
                for (int nt = 0; nt < 2; nt++)
                    asm volatile(
                        "mma.sync.aligned.m16n8k8.row.col.f32.tf32.tf32.f32 "
                        "{%0,%1,%2,%3}, {%4,%5,%6,%7}, {%8,%9}, {%0,%1,%2,%3};"
                        : "+f"(c[mt][nt][0]), "+f"(c[mt][nt][1]),
                          "+f"(c[mt][nt][2]), "+f"(c[mt][nt][3])
                        : "r"(A[mt][0]), "r"(A[mt][1]), "r"(A[mt][2]), "r"(A[mt][3]),
                          "r"(B[nt][0]), "r"(B[nt][1]));
        }
        __syncthreads();
    }
    #undef GLOAD

    #pragma unroll
    for (int mt = 0; mt < 2; mt++)
        #pragma unroll
        for (int nt = 0; nt < 2; nt++) {
            int o = ocol0 + warp * 16 + nt * 8 + qc * 2;
            int b0 = mt * 16 + qr;
            *(float2*)(&Y[(size_t)b0 * ldY + o])       = make_float2(c[mt][nt][0], c[mt][nt][1]);
            *(float2*)(&Y[(size_t)(b0 + 8) * ldY + o]) = make_float2(c[mt][nt][2], c[mt][nt][3]);
        }
}

__global__ __launch_bounds__(128) void gemm_qkv_kernel(
    const float* __restrict__ X, const float* __restrict__ Wq,
    const float* __restrict__ Wk, const float* __restrict__ Wv)
{
    __shared__ __align__(16) float xs[2][NB * XSTR];
    __shared__ __align__(16) float ws[2][GOB * WSTR];
    int o0 = blockIdx.x * GOB;
    int sp = blockIdx.y;
    const float* W;
    if (o0 < OQ)            W = Wq + (size_t)o0 * HID;
    else if (o0 < OQ + OKV) W = Wk + (size_t)(o0 - OQ) * HID;
    else                    W = Wv + (size_t)(o0 - OQ - OKV) * HID;
    gemm_mma_tile(X, W, g_qkv_part[sp], OQKV, o0, sp * KS,
                  xs[0], xs[1], ws[0], ws[1]);
}

__global__ __launch_bounds__(128) void gemm_wo_kernel(const float* __restrict__ Wo)
{
    __shared__ __align__(16) float xs[2][NB * XSTR];
    __shared__ __align__(16) float ws[2][GOB * WSTR];
    int o0 = blockIdx.x * GOB;
    int sp = blockIdx.y;
    gemm_mma_tile(g_ctx, Wo + (size_t)o0 * HID, g_out_part[sp], HID, o0, sp * KS,
                  xs[0], xs[1], ws[0], ws[1]);
}

// -------- reduce split-K partials + RoPE (q,k) / identity (v) ----------------
__global__ __launch_bounds__(128) void reduce_rope_kernel(
    const int* __restrict__ pos, const float* __restrict__ cosc,
    const float* __restrict__ sinc)
{
    int u = blockIdx.x % 48;
    int b = blockIdx.x / 48;
    int t = threadIdx.x;
    size_t base = (size_t)b * OQKV + u * 128;
    if (u < 40) {
        if (t < 64) {
            float x1 = 0.f, x2 = 0.f;
            #pragma unroll
            for (int s = 0; s < SPLITK; s++) {
                x1 += g_qkv_part[s][base + t];
                x2 += g_qkv_part[s][base + t + 64];
            }
            int p = pos[b];
            float c = cosc[p * 64 + t], sn = sinc[p * 64 + t];
            g_qkv[base + t]      = x1 * c - x2 * sn;
            g_qkv[base + t + 64] = x2 * c + x1 * sn;
        }
    } else {
        float x = 0.f;
        #pragma unroll
        for (int s = 0; s < SPLITK; s++) x += g_qkv_part[s][base + t];
        g_qkv[base + t] = x;
    }
}

__global__ __launch_bounds__(128) void reduce_out_kernel(float* __restrict__ out)
{
    int i = (blockIdx.x * 128 + threadIdx.x) * 4;
    float4 acc = make_float4(0.f, 0.f, 0.f, 0.f);
    #pragma unroll
    for (int s = 0; s < SPLITK; s++) {
        float4 v = *(const float4*)(&g_out_part[s][i]);
        acc.x += v.x; acc.y += v.y; acc.z += v.z; acc.w += v.w;
    }
    *(float4*)(&out[i]) = acc;
}

// Profiling shims: gemm_qkv lands on captured launch idx 3.
__global__ void profile_shim_kernel() { if (threadIdx.x == 1024) g_dummy_sink = 1; }

// ---------------- fused flash-decode split + KV-cache copy -------------------
__global__ __launch_bounds__(128) void attn_kernel(
    const float* __restrict__ pk, const float* __restrict__ pv,
    const float* __restrict__ bias, float* __restrict__ out_k,
    float* __restrict__ out_v)
{
    extern __shared__ __align__(16) float smem[];
    float* qs = smem;
    float* sbias = smem + NG*DHD;
    float* bufK[2] = { smem + NG*DHD + CHUNK, smem + NG*DHD + CHUNK + TILE_KF };
    float* bufV[2] = { smem + NG*DHD + CHUNK + 2*TILE_KF,
                       smem + NG*DHD + CHUNK + 2*TILE_KF + TILE_VF };

    int split = blockIdx.x, h = blockIdx.y, b = blockIdx.z;
    int t = threadIdx.x, warp = t >> 5, lane = t & 31;

    const float* kbase = pk + (size_t)(b * NHKV + h) * PAST * DHD;
    const float* vbase = pv + (size_t)(b * NHKV + h) * PAST * DHD;
    float* okbase = out_k + (size_t)(b * NHKV + h) * TTOT * DHD;
    float* ovbase = out_v + (size_t)(b * NHKV + h) * TTOT * DHD;

    uint32_t sm0 = (uint32_t)__cvta_generic_to_shared(smem);
    uint32_t kOff[2] = { sm0 + (uint32_t)(NG*DHD + CHUNK)*4,
                         sm0 + (uint32_t)(NG*DHD + CHUNK + TILE_KF)*4 };
    uint32_t vOff[2] = { sm0 + (uint32_t)(NG*DHD + CHUNK + 2*TILE_KF)*4,
                         sm0 + (uint32_t)(NG*DHD + CHUNK + 2*TILE_KF + TILE_VF)*4 };

    int tstart = split * CHUNK;

    {
        #pragma unroll
        for (int it = 0; it < 8; it++) {
            int idx = it * 128 + t;
            int rr = idx >> 5, c4 = idx & 31;
            size_t go = (size_t)(tstart + rr) * DHD + c4 * 4;
            cp_async16(kOff[0] + (uint32_t)(rr * KPAD + c4 * 4) * 4, kbase + go);
            cp_async16(vOff[0] + (uint32_t)(rr * DHD  + c4 * 4) * 4, vbase + go);
        }
        asm volatile("cp.async.commit_group;" ::: "memory");
    }

    for (int i = t; i < NG * DHD; i += 128)
        qs[i] = g_qkv[(size_t)b * OQKV + (h * NG + (i >> 7)) * DHD + (i & 127)];
    sbias[t] = bias[(size_t)b * TTOT + tstart + t];

    float m = -INFINITY, l = 0.f;
    u64 a01 = 0ull, a23 = 0ull;

    for (int ti = 0; ti < NT; ti++) {
        int t0 = tstart + ti * KTILE;
        int cur = ti & 1;
        if (ti + 1 < NT) {
            int nxt = cur ^ 1;
            int t1 = t0 + KTILE;
            #pragma unroll
            for (int it = 0; it < 8; it++) {
                int idx = it * 128 + t;
                int rr = idx >> 5, c4 = idx & 31;
                size_t go = (size_t)(t1 + rr) * DHD + c4 * 4;
                cp_async16(kOff[nxt] + (uint32_t)(rr * KPAD + c4 * 4) * 4, kbase + go);
                cp_async16(vOff[nxt] + (uint32_t)(rr * DHD  + c4 * 4) * 4, vbase + go);
            }
            asm volatile("cp.async.commit_group;" ::: "memory");
            asm volatile("cp.async.wait_group 1;" ::: "memory");
        } else {
            asm volatile("cp.async.wait_group 0;" ::: "memory");
        }
        __syncthreads();

        const float* kb = bufK[cur];
        const float* vb = bufV[cur];

        if (t == 0) {
            asm volatile("fence.proxy.async.shared::cta;" ::: "memory");
            asm volatile("cp.async.bulk.global.shared::cta.bulk_group [%0], [%1], %2;"
                         :: "l"(ovbase + (size_t)t0 * DHD), "r"(vOff[cur]),
                            "r"((int)(TILE_VF * 4)) : "memory");
            asm volatile("cp.async.bulk.commit_group;" ::: "memory");
        }

        const float* qg = qs + warp * DHD;
        u64 s01 = 0ull, s23 = 0ull;
        #pragma unroll
        for (int d4 = 0; d4 < 32; d4++) {
            ulonglong2 qv = *(const ulonglong2*)(qg + d4 * 4);
            ulonglong2 kv = *(const ulonglong2*)(kb + (size_t)lane * KPAD + d4 * 4);
            s01 = fma2(qv.x, kv.x, s01);
            s23 = fma2(qv.y, kv.y, s23);
        }
        float2 sa = un2(s01), sb = un2(s23);
        float s = ((sa.x + sa.y) + (sb.x + sb.y)) * ATT_SCALE + sbias[ti * KTILE + lane];

        float mt = warp_max(s);
        float mnew = fmaxf(m, mt);
        float alpha = __expf(m - mnew);
        float p = __expf(s - mnew);
        l = l * alpha + warp_sum(p);
        m = mnew;
        u64 al2 = dup2(alpha);
        a01 = fma2(a01, al2, 0ull);
        a23 = fma2(a23, al2, 0ull);
        #pragma unroll
        for (int j = 0; j < KTILE; j++) {
            float pj = __shfl_sync(0xffffffffu, p, j);
            u64 pj2 = dup2(pj);
            ulonglong2 vv = *(const ulonglong2*)(vb + j * DHD + lane * 4);
            a01 = fma2(pj2, vv.x, a01);
            a23 = fma2(pj2, vv.y, a23);
        }

        #pragma unroll
        for (int it = 0; it < 8; it++) {
            int idx = it * 128 + t;
            int rr = idx >> 5, c4 = idx & 31;
            __stcs((float4*)(okbase + (size_t)(t0 + rr) * DHD + c4 * 4),
                   *(const float4*)(kb + rr * KPAD + c4 * 4));
        }

        if (t == 0)
            asm volatile("cp.async.bulk.wait_group.read 0;" ::: "memory");
        __syncthreads();
    }

    float2 f0 = un2(a01), f1 = un2(a23);
    float4 a = make_float4(f0.x, f0.y, f1.x, f1.y);

    if (split == NSPLIT - 1) {
        const float* kn = &g_qkv[(size_t)b * OQKV + OQ + h * DHD];
        const float* vn = &g_qkv[(size_t)b * OQKV + OQ + OKV + h * DHD];
        if (t < 32)      *(float4*)(okbase + (size_t)PAST * DHD + t * 4) = *(const float4*)(kn + t * 4);
        else if (t < 64) *(float4*)(ovbase + (size_t)PAST * DHD + (t - 32) * 4) = *(const float4*)(vn + (t - 32) * 4);
        float sp = 0.f;
        #pragma unroll
        for (int i = lane; i < DHD; i += 32) sp += qs[warp * DHD + i] * kn[i];
        sp = warp_sum(sp) * ATT_SCALE + bias[(size_t)b * TTOT + PAST];
        float mnew = fmaxf(m, sp);
        float alpha = __expf(m - mnew);
        float p = __expf(sp - mnew);
        l = l * alpha + p;
        m = mnew;
        float4 vv = *(const float4*)(vn + lane * 4);
        a.x = a.x * alpha + p * vv.x; a.y = a.y * alpha + p * vv.y;
        a.z = a.z * alpha + p * vv.z; a.w = a.w * alpha + p * vv.w;
    }

    int pidx = ((b * NHKV + h) * NG + warp) * NSPLIT + split;
    if (lane == 0) { g_pm[pidx] = m; g_pl[pidx] = l; }
    *(float4*)(&g_pacc[(size_t)pidx * DHD + lane * 4]) = a;

    if (t == 0)
        asm volatile("cp.async.bulk.wait_group 0;" ::: "memory");
}

// ---------------- combine split partials -> context --------------------------
__global__ __launch_bounds__(128) void combine_kernel()
{
    int bh = blockIdx.x;
    int b = bh / NHQ, hq = bh % NHQ;
    int h = hq / NG, g = hq % NG;
    int pbase = ((b * NHKV + h) * NG + g) * NSPLIT;
    int d = threadIdx.x;

    float M = -INFINITY;
    #pragma unroll
    for (int s = 0; s < NSPLIT; s++) M = fmaxf(M, g_pm[pbase + s]);
    float L0 = 0.f, L1 = 0.f, c0 = 0.f, c1 = 0.f;
    #pragma unroll
    for (int s = 0; s < NSPLIT; s += 2) {
        float w0 = __expf(g_pm[pbase + s]     - M);
        float w1 = __expf(g_pm[pbase + s + 1] - M);
        L0 += w0 * g_pl[pbase + s];
        L1 += w1 * g_pl[pbase + s + 1];
        c0 += w0 * g_pacc[(size_t)(pbase + s)     * DHD + d];
        c1 += w1 * g_pacc[(size_t)(pbase + s + 1) * DHD + d];
    }
    g_ctx[(size_t)bh * DHD + d] = (c0 + c1) / (L0 + L1);
}

// ---------------- launch ----------------------------------------------------
extern "C" void kernel_launch(void* const* d_in, const int* in_sizes, int n_in,
                              void* d_out, int out_size)
{
    const float* hidden = (const float*)d_in[0];
    const float* bias   = (const float*)d_in[1];
    const int*   pos    = (const int*)d_in[2];
    const float* cosc   = (const float*)d_in[3];
    const float* sinc   = (const float*)d_in[4];
    const float* pk     = (const float*)d_in[5];
    const float* pv     = (const float*)d_in[6];
    const float* Wq     = (const float*)d_in[7];
    const float* Wk     = (const float*)d_in[8];
    const float* Wv     = (const float*)d_in[9];
    const float* Wo     = (const float*)d_in[10];

    float* out = (float*)d_out;
    size_t kv_elems = (size_t)NB * NHKV * TTOT * DHD;
    float* out_k = out + (size_t)NB * HID;
    float* out_v = out_k + kv_elems;

    static bool attr_set = false;
    if (!attr_set) {
        cudaFuncSetAttribute(attn_kernel, cudaFuncAttributeMaxDynamicSharedMemorySize,
                             ATTN_SMEM_BYTES);
        attr_set = true;
    }

    profile_shim_kernel<<<1, 32>>>();
    profile_shim_kernel<<<1, 32>>>();
    profile_shim_kernel<<<1, 32>>>();   // gemm_qkv lands on captured launch idx 3
    gemm_qkv_kernel<<<dim3(OQKV / GOB, SPLITK), 128>>>(hidden, Wq, Wk, Wv);
    reduce_rope_kernel<<<NB * 48, 128>>>(pos, cosc, sinc);
    attn_kernel<<<dim3(NSPLIT, NHKV, NB), 128, ATTN_SMEM_BYTES>>>(pk, pv, bias, out_k, out_v);
    combine_kernel<<<NB * NHQ, 128>>>();
    gemm_wo_kernel<<<dim3(HID / GOB, SPLITK), 128>>>(Wo);
    reduce_out_kernel<<<NB * HID / 512, 128>>>(out);
}

// round 12
// speedup vs baseline: 1.0239x; 1.0077x over previous
#include <cuda_runtime.h>
#include <math.h>
#include <stdint.h>

#define NB 32
#define NHQ 32
#define NHKV 8
#define NG 4
#define DHD 128
#define HID 4096
#define PAST 4096
#define TTOT 4097
#define NSPLIT 32
#define CHUNK (PAST / NSPLIT)      // 128
#define KTILE 32
#define NT (CHUNK / KTILE)         // 4
#define SPLITK 16
#define KS (HID / SPLITK)          // 256
#define ATT_SCALE 0.08838834764831845f
#define OQ 4096
#define OKV 1024
#define OQKV 6144

#define KPAD 132
#define TILE_KF (KTILE * KPAD)
#define TILE_VF (KTILE * DHD)
#define ATTN_SMEM_F (NG * DHD + CHUNK + 2 * TILE_KF + 2 * TILE_VF)
#define ATTN_SMEM_BYTES (ATTN_SMEM_F * 4)

// ---- mma.sync tf32 GEMM: block = 32 b x 64 o, stage = 32 k, 3-stage pipe ----
#define GOB 64
#define GKS 32
#define GNSTG (KS / GKS)           // 8 stages
#define XSTR 36
#define WSTR 36

// ---------------- scratch ----------------------------------------------------
static __device__ float g_qkv_part[SPLITK][NB * OQKV];
static __device__ float g_qkv[NB * OQKV];
static __device__ float g_out_part[SPLITK][NB * HID];
static __device__ float g_pm[NB * NHKV * NG * NSPLIT];
static __device__ float g_pl[NB * NHKV * NG * NSPLIT];
static __device__ float g_pacc[NB * NHKV * NG * NSPLIT * DHD];
static __device__ float g_ctx[NB * NHQ * DHD];

typedef unsigned long long u64;

__device__ __forceinline__ u64 fma2(u64 a, u64 b, u64 c) {
    u64 d;
    asm("fma.rn.f32x2 %0, %1, %2, %3;" : "=l"(d) : "l"(a), "l"(b), "l"(c));
    return d;
}
__device__ __forceinline__ u64 dup2(float x) {
    u64 d; unsigned xi = __float_as_uint(x);
    asm("mov.b64 %0, {%1, %1};" : "=l"(d) : "r"(xi));
    return d;
}
__device__ __forceinline__ float2 un2(u64 v) {
    float2 r;
    asm("mov.b64 {%0, %1}, %2;" : "=f"(r.x), "=f"(r.y) : "l"(v));
    return r;
}
__device__ __forceinline__ float warp_max(float v) {
    #pragma unroll
    for (int o = 16; o > 0; o >>= 1) v = fmaxf(v, __shfl_xor_sync(0xffffffffu, v, o));
    return v;
}
__device__ __forceinline__ float warp_sum(float v) {
    #pragma unroll
    for (int o = 16; o > 0; o >>= 1) v += __shfl_xor_sync(0xffffffffu, v, o);
    return v;
}
__device__ __forceinline__ void cp_async16(uint32_t saddr, const void* gptr) {
    asm volatile("cp.async.cg.shared.global [%0], [%1], 16;" :: "r"(saddr), "l"(gptr));
}
__device__ __forceinline__ uint32_t to_tf32(float f) {
    uint32_t u;
    asm("cvt.rna.tf32.f32 %0, %1;" : "=r"(u) : "f"(f));
    return u;
}

// ---------------- tf32 mma.sync GEMM tile (3-stage pipeline) ------------------
__device__ __forceinline__ void gemm_mma_tile(
    const float* __restrict__ X, const float* __restrict__ W,
    float* __restrict__ Y, int ldY, int ocol0, int k0,
    float (*xs)[NB * XSTR], float (*ws)[GOB * WSTR])
{
    int t = threadIdx.x, warp = t >> 5, lane = t & 31;
    int qr = lane >> 2, qc = lane & 3;

    float c[2][2][4];
    #pragma unroll
    for (int mt = 0; mt < 2; mt++)
        #pragma unroll
        for (int nt = 0; nt < 2; nt++)
            #pragma unroll
            for (int i = 0; i < 4; i++) c[mt][nt][i] = 0.f;

    uint32_t xsa[3], wsa[3];
    #pragma unroll
    for (int i = 0; i < 3; i++) {
        xsa[i] = (uint32_t)__cvta_generic_to_shared(xs[i]);
        wsa[i] = (uint32_t)__cvta_generic_to_shared(ws[i]);
    }

    #define GLOAD(s_) do {                                                        \
        int buf = (s_) % 3;                                                       \
        int kk = k0 + (s_) * GKS;                                                 \
        _Pragma("unroll")                                                         \
        for (int it = 0; it < 2; it++) {                                          \
            int idx = it * 128 + t; int row = idx >> 3, c4 = idx & 7;             \
            cp_async16(xsa[buf] + (uint32_t)(row * XSTR + c4 * 4) * 4,            \
                       X + (size_t)row * HID + kk + c4 * 4);                      \
        }                                                                         \
        _Pragma("unroll")                                                         \
        for (int it = 0; it < 4; it++) {                                          \
            int idx = it * 128 + t; int row = idx >> 3, c4 = idx & 7;             \
            cp_async16(wsa[buf] + (uint32_t)(row * WSTR + c4 * 4) * 4,            \
                       W + (size_t)row * HID + kk + c4 * 4);                      \
        }                                                                         \
        asm volatile("cp.async.commit_group;" ::: "memory");                      \
    } while (0)

    GLOAD(0);
    GLOAD(1);
    for (int s = 0; s < GNSTG; s++) {
        if (s + 2 < GNSTG) {
            GLOAD(s + 2);
            asm volatile("cp.async.wait_group 2;" ::: "memory");
        } else if (s + 1 < GNSTG) {
            asm volatile("cp.async.wait_group 1;" ::: "memory");
        } else {
            asm volatile("cp.async.wait_group 0;" ::: "memory");
        }
        __syncthreads();
        const float* xb = xs[s % 3];
        const float* wb = ws[s % 3];
        #pragma unroll
        for (int ks = 0; ks < 4; ks++) {
            int kc = ks * 8;
            uint32_t A[2][4], B[2][2];
            #pragma unroll
            for (int mt = 0; mt < 2; mt++) {
                int r0 = mt * 16 + qr;
                A[mt][0] = to_tf32(xb[(r0)     * XSTR + kc + qc]);
                A[mt][1] = to_tf32(xb[(r0 + 8) * XSTR + kc + qc]);
                A[mt][2] = to_tf32(xb[(r0)     * XSTR + kc + qc + 4]);
                A[mt][3] = to_tf32(xb[(r0 + 8) * XSTR + kc + qc + 4]);
            }
            #pragma unroll
            for (int nt = 0; nt < 2; nt++) {
                int o = warp * 16 + nt * 8 + qr;
                B[nt][0] = to_tf32(wb[o * WSTR + kc + qc]);
                B[nt][1] = to_tf32(wb[o * WSTR + kc + qc + 4]);
            }
            #pragma unroll
            for (int mt = 0; mt < 2; mt++)
                #pragma unroll
                for (int nt = 0; nt < 2; nt++)
                    asm volatile(
                        "mma.sync.aligned.m16n8k8.row.col.f32.tf32.tf32.f32 "
                        "{%0,%1,%2,%3}, {%4,%5,%6,%7}, {%8,%9}, {%0,%1,%2,%3};"
                        : "+f"(c[mt][nt][0]), "+f"(c[mt][nt][1]),
                          "+f"(c[mt][nt][2]), "+f"(c[mt][nt][3])
                        : "r"(A[mt][0]), "r"(A[mt][1]), "r"(A[mt][2]), "r"(A[mt][3]),
                          "r"(B[nt][0]), "r"(B[nt][1]));
        }
        __syncthreads();
    }
    #undef GLOAD

    #pragma unroll
    for (int mt = 0; mt < 2; mt++)
        #pragma unroll
        for (int nt = 0; nt < 2; nt++) {
            int o = ocol0 + warp * 16 + nt * 8 + qc * 2;
            int b0 = mt * 16 + qr;
            *(float2*)(&Y[(size_t)b0 * ldY + o])       = make_float2(c[mt][nt][0], c[mt][nt][1]);
            *(float2*)(&Y[(size_t)(b0 + 8) * ldY + o]) = make_float2(c[mt][nt][2], c[mt][nt][3]);
        }
}

__global__ __launch_bounds__(128) void gemm_qkv_kernel(
    const float* __restrict__ X, const float* __restrict__ Wq,
    const float* __restrict__ Wk, const float* __restrict__ Wv)
{
    __shared__ __align__(16) float xs[3][NB * XSTR];
    __shared__ __align__(16) float ws[3][GOB * WSTR];
    int o0 = blockIdx.x * GOB;
    int sp = blockIdx.y;
    const float* W;
    if (o0 < OQ)            W = Wq + (size_t)o0 * HID;
    else if (o0 < OQ + OKV) W = Wk + (size_t)(o0 - OQ) * HID;
    else                    W = Wv + (size_t)(o0 - OQ - OKV) * HID;
    gemm_mma_tile(X, W, g_qkv_part[sp], OQKV, o0, sp * KS, xs, ws);
}

__global__ __launch_bounds__(128) void gemm_wo_kernel(const float* __restrict__ Wo)
{
    __shared__ __align__(16) float xs[3][NB * XSTR];
    __shared__ __align__(16) float ws[3][GOB * WSTR];
    int o0 = blockIdx.x * GOB;
    int sp = blockIdx.y;
    gemm_mma_tile(g_ctx, Wo + (size_t)o0 * HID, g_out_part[sp], HID, o0, sp * KS, xs, ws);
}

// -------- reduce split-K partials + RoPE (q,k) / identity (v) ----------------
__global__ __launch_bounds__(128) void reduce_rope_kernel(
    const int* __restrict__ pos, const float* __restrict__ cosc,
    const float* __restrict__ sinc)
{
    int u = blockIdx.x % 48;
    int b = blockIdx.x / 48;
    int t = threadIdx.x;
    size_t base = (size_t)b * OQKV + u * 128;
    if (u < 40) {
        if (t < 64) {
            float x1 = 0.f, x2 = 0.f;
            #pragma unroll
            for (int s = 0; s < SPLITK; s++) {
                x1 += g_qkv_part[s][base + t];
                x2 += g_qkv_part[s][base + t + 64];
            }
            int p = pos[b];
            float c = cosc[p * 64 + t], sn = sinc[p * 64 + t];
            g_qkv[base + t]      = x1 * c - x2 * sn;
            g_qkv[base + t + 64] = x2 * c + x1 * sn;
        }
    } else {
        float x = 0.f;
        #pragma unroll
        for (int s = 0; s < SPLITK; s++) x += g_qkv_part[s][base + t];
        g_qkv[base + t] = x;
    }
}

__global__ __launch_bounds__(128) void reduce_out_kernel(float* __restrict__ out)
{
    int i = (blockIdx.x * 128 + threadIdx.x) * 4;
    float4 acc = make_float4(0.f, 0.f, 0.f, 0.f);
    #pragma unroll
    for (int s = 0; s < SPLITK; s++) {
        float4 v = *(const float4*)(&g_out_part[s][i]);
        acc.x += v.x; acc.y += v.y; acc.z += v.z; acc.w += v.w;
    }
    *(float4*)(&out[i]) = acc;
}

// ---------------- fused flash-decode split + KV-cache copy -------------------
__global__ __launch_bounds__(128) void attn_kernel(
    const float* __restrict__ pk, const float* __restrict__ pv,
    const float* __restrict__ bias, float* __restrict__ out_k,
    float* __restrict__ out_v)
{
    extern __shared__ __align__(16) float smem[];
    float* qs = smem;
    float* sbias = smem + NG*DHD;
    float* bufK[2] = { smem + NG*DHD + CHUNK, smem + NG*DHD + CHUNK + TILE_KF };
    float* bufV[2] = { smem + NG*DHD + CHUNK + 2*TILE_KF,
                       smem + NG*DHD + CHUNK + 2*TILE_KF + TILE_VF };

    int split = blockIdx.x, h = blockIdx.y, b = blockIdx.z;
    int t = threadIdx.x, warp = t >> 5, lane = t & 31;

    const float* kbase = pk + (size_t)(b * NHKV + h) * PAST * DHD;
    const float* vbase = pv + (size_t)(b * NHKV + h) * PAST * DHD;
    float* okbase = out_k + (size_t)(b * NHKV + h) * TTOT * DHD;
    float* ovbase = out_v + (size_t)(b * NHKV + h) * TTOT * DHD;

    uint32_t sm0 = (uint32_t)__cvta_generic_to_shared(smem);
    uint32_t kOff[2] = { sm0 + (uint32_t)(NG*DHD + CHUNK)*4,
                         sm0 + (uint32_t)(NG*DHD + CHUNK + TILE_KF)*4 };
    uint32_t vOff[2] = { sm0 + (uint32_t)(NG*DHD + CHUNK + 2*TILE_KF)*4,
                         sm0 + (uint32_t)(NG*DHD + CHUNK + 2*TILE_KF + TILE_VF)*4 };

    int tstart = split * CHUNK;

    {
        #pragma unroll
        for (int it = 0; it < 8; it++) {
            int idx = it * 128 + t;
            int rr = idx >> 5, c4 = idx & 31;
            size_t go = (size_t)(tstart + rr) * DHD + c4 * 4;
            cp_async16(kOff[0] + (uint32_t)(rr * KPAD + c4 * 4) * 4, kbase + go);
            cp_async16(vOff[0] + (uint32_t)(rr * DHD  + c4 * 4) * 4, vbase + go);
        }
        asm volatile("cp.async.commit_group;" ::: "memory");
    }

    for (int i = t; i < NG * DHD; i += 128)
        qs[i] = g_qkv[(size_t)b * OQKV + (h * NG + (i >> 7)) * DHD + (i & 127)];
    sbias[t] = bias[(size_t)b * TTOT + tstart + t];

    float m = -INFINITY, l = 0.f;
    u64 a01 = 0ull, a23 = 0ull;

    for (int ti = 0; ti < NT; ti++) {
        int t0 = tstart + ti * KTILE;
        int cur = ti & 1;
        if (ti + 1 < NT) {
            int nxt = cur ^ 1;
            int t1 = t0 + KTILE;
            #pragma unroll
            for (int it = 0; it < 8; it++) {
                int idx = it * 128 + t;
                int rr = idx >> 5, c4 = idx & 31;
                size_t go = (size_t)(t1 + rr) * DHD + c4 * 4;
                cp_async16(kOff[nxt] + (uint32_t)(rr * KPAD + c4 * 4) * 4, kbase + go);
                cp_async16(vOff[nxt] + (uint32_t)(rr * DHD  + c4 * 4) * 4, vbase + go);
            }
            asm volatile("cp.async.commit_group;" ::: "memory");
            asm volatile("cp.async.wait_group 1;" ::: "memory");
        } else {
            asm volatile("cp.async.wait_group 0;" ::: "memory");
        }
        __syncthreads();

        const float* kb = bufK[cur];
        const float* vb = bufV[cur];

        if (t == 0) {
            asm volatile("fence.proxy.async.shared::cta;" ::: "memory");
            asm volatile("cp.async.bulk.global.shared::cta.bulk_group [%0], [%1], %2;"
                         :: "l"(ovbase + (size_t)t0 * DHD), "r"(vOff[cur]),
                            "r"((int)(TILE_VF * 4)) : "memory");
            asm volatile("cp.async.bulk.commit_group;" ::: "memory");
        }

        const float* qg = qs + warp * DHD;
        u64 s01 = 0ull, s23 = 0ull;
        #pragma unroll
        for (int d4 = 0; d4 < 32; d4++) {
            ulonglong2 qv = *(const ulonglong2*)(qg + d4 * 4);
            ulonglong2 kv = *(const ulonglong2*)(kb + (size_t)lane * KPAD + d4 * 4);
            s01 = fma2(qv.x, kv.x, s01);
            s23 = fma2(qv.y, kv.y, s23);
        }
        float2 sa = un2(s01), sb = un2(s23);
        float s = ((sa.x + sa.y) + (sb.x + sb.y)) * ATT_SCALE + sbias[ti * KTILE + lane];

        float mt = warp_max(s);
        float mnew = fmaxf(m, mt);
        float alpha = __expf(m - mnew);
        float p = __expf(s - mnew);
        l = l * alpha + warp_sum(p);
        m = mnew;
        u64 al2 = dup2(alpha);
        a01 = fma2(a01, al2, 0ull);
        a23 = fma2(a23, al2, 0ull);
        #pragma unroll
        for (int j = 0; j < KTILE; j++) {
            float pj = __shfl_sync(0xffffffffu, p, j);
            u64 pj2 = dup2(pj);
            ulonglong2 vv = *(const ulonglong2*)(vb + j * DHD + lane * 4);
            a01 = fma2(pj2, vv.x, a01);
            a23 = fma2(pj2, vv.y, a23);
        }

        #pragma unroll
        for (int it = 0; it < 8; it++) {
            int idx = it * 128 + t;
            int rr = idx >> 5, c4 = idx & 31;
            __stcs((float4*)(okbase + (size_t)(t0 + rr) * DHD + c4 * 4),
                   *(const float4*)(kb + rr * KPAD + c4 * 4));
        }

        if (t == 0)
            asm volatile("cp.async.bulk.wait_group.read 0;" ::: "memory");
        __syncthreads();
    }

    float2 f0 = un2(a01), f1 = un2(a23);
    float4 a = make_float4(f0.x, f0.y, f1.x, f1.y);

    if (split == NSPLIT - 1) {
        const float* kn = &g_qkv[(size_t)b * OQKV + OQ + h * DHD];
        const float* vn = &g_qkv[(size_t)b * OQKV + OQ + OKV + h * DHD];
        if (t < 32)      *(float4*)(okbase + (size_t)PAST * DHD + t * 4) = *(const float4*)(kn + t * 4);
        else if (t < 64) *(float4*)(ovbase + (size_t)PAST * DHD + (t - 32) * 4) = *(const float4*)(vn + (t - 32) * 4);
        float sp = 0.f;
        #pragma unroll
        for (int i = lane; i < DHD; i += 32) sp += qs[warp * DHD + i] * kn[i];
        sp = warp_sum(sp) * ATT_SCALE + bias[(size_t)b * TTOT + PAST];
        float mnew = fmaxf(m, sp);
        float alpha = __expf(m - mnew);
        float p = __expf(sp - mnew);
        l = l * alpha + p;
        m = mnew;
        float4 vv = *(const float4*)(vn + lane * 4);
        a.x = a.x * alpha + p * vv.x; a.y = a.y * alpha + p * vv.y;
        a.z = a.z * alpha + p * vv.z; a.w = a.w * alpha + p * vv.w;
    }

    int pidx = ((b * NHKV + h) * NG + warp) * NSPLIT + split;
    if (lane == 0) { g_pm[pidx] = m; g_pl[pidx] = l; }
    *(float4*)(&g_pacc[(size_t)pidx * DHD + lane * 4]) = a;

    if (t == 0)
        asm volatile("cp.async.bulk.wait_group 0;" ::: "memory");
}

// ---------------- combine split partials -> context --------------------------
__global__ __launch_bounds__(128) void combine_kernel()
{
    int bh = blockIdx.x;
    int b = bh / NHQ, hq = bh % NHQ;
    int h = hq / NG, g = hq % NG;
    int pbase = ((b * NHKV + h) * NG + g) * NSPLIT;
    int d = threadIdx.x;

    float M = -INFINITY;
    #pragma unroll
    for (int s = 0; s < NSPLIT; s++) M = fmaxf(M, g_pm[pbase + s]);
    float L0 = 0.f, L1 = 0.f, c0 = 0.f, c1 = 0.f;
    #pragma unroll
    for (int s = 0; s < NSPLIT; s += 2) {
        float w0 = __expf(g_pm[pbase + s]     - M);
        float w1 = __expf(g_pm[pbase + s + 1] - M);
        L0 += w0 * g_pl[pbase + s];
        L1 += w1 * g_pl[pbase + s + 1];
        c0 += w0 * g_pacc[(size_t)(pbase + s)     * DHD + d];
        c1 += w1 * g_pacc[(size_t)(pbase + s + 1) * DHD + d];
    }
    g_ctx[(size_t)bh * DHD + d] = (c0 + c1) / (L0 + L1);
}

// ---------------- launch ----------------------------------------------------
extern "C" void kernel_launch(void* const* d_in, const int* in_sizes, int n_in,
                              void* d_out, int out_size)
{
    const float* hidden = (const float*)d_in[0];
    const float* bias   = (const float*)d_in[1];
    const int*   pos    = (const int*)d_in[2];
    const float* cosc   = (const float*)d_in[3];
    const float* sinc   = (const float*)d_in[4];
    const float* pk     = (const float*)d_in[5];
    const float* pv     = (const float*)d_in[6];
    const float* Wq     = (const float*)d_in[7];
    const float* Wk     = (const float*)d_in[8];
    const float* Wv     = (const float*)d_in[9];
    const float* Wo     = (const float*)d_in[10];

    float* out = (float*)d_out;
    size_t kv_elems = (size_t)NB * NHKV * TTOT * DHD;
    float* out_k = out + (size_t)NB * HID;
    float* out_v = out_k + kv_elems;

    static bool attr_set = false;
    if (!attr_set) {
        cudaFuncSetAttribute(attn_kernel, cudaFuncAttributeMaxDynamicSharedMemorySize,
                             ATTN_SMEM_BYTES);
        attr_set = true;
    }

    gemm_qkv_kernel<<<dim3(OQKV / GOB, SPLITK), 128>>>(hidden, Wq, Wk, Wv);
    reduce_rope_kernel<<<NB * 48, 128>>>(pos, cosc, sinc);
    attn_kernel<<<dim3(NSPLIT, NHKV, NB), 128, ATTN_SMEM_BYTES>>>(pk, pv, bias, out_k, out_v);
    combine_kernel<<<NB * NHQ, 128>>>();
    gemm_wo_kernel<<<dim3(HID / GOB, SPLITK), 128>>>(Wo);
    reduce_out_kernel<<<NB * HID / 512, 128>>>(out);
}

// round 13
// speedup vs baseline: 1.0417x; 1.0173x over previous
#include <cuda_runtime.h>
#include <math.h>
#include <stdint.h>

#define NB 32
#define NHQ 32
#define NHKV 8
#define NG 4
#define DHD 128
#define HID 4096
#define PAST 4096
#define TTOT 4097
#define NSPLIT 16
#define CHUNK (PAST / NSPLIT)      // 256
#define KTILE 32
#define NT (CHUNK / KTILE)         // 8
#define SPLITK 16
#define KS (HID / SPLITK)          // 256
#define ATT_SCALE 0.08838834764831845f
#define OQ 4096
#define OKV 1024
#define OQKV 6144

#define KPAD 132
#define TILE_KF (KTILE * KPAD)
#define TILE_VF (KTILE * DHD)
#define ATTN_SMEM_F (NG * DHD + CHUNK + 2 * TILE_KF + 2 * TILE_VF)
#define ATTN_SMEM_BYTES (ATTN_SMEM_F * 4)

// ---- mma.sync tf32 GEMM: block = 32 b x 64 o, stage = 32 k, 3-stage pipe ----
#define GOB 64
#define GKS 32
#define GNSTG (KS / GKS)           // 8 stages
#define XSTR 36
#define WSTR 36

// ---------------- scratch ----------------------------------------------------
static __device__ float g_qkv_part[SPLITK][NB * OQKV];
static __device__ float g_qkv[NB * OQKV];
static __device__ float g_out_part[SPLITK][NB * HID];
static __device__ float g_pm[NB * NHKV * NG * NSPLIT];
static __device__ float g_pl[NB * NHKV * NG * NSPLIT];
static __device__ float g_pacc[NB * NHKV * NG * NSPLIT * DHD];
static __device__ float g_ctx[NB * NHQ * DHD];

typedef unsigned long long u64;

__device__ __forceinline__ u64 fma2(u64 a, u64 b, u64 c) {
    u64 d;
    asm("fma.rn.f32x2 %0, %1, %2, %3;" : "=l"(d) : "l"(a), "l"(b), "l"(c));
    return d;
}
__device__ __forceinline__ u64 dup2(float x) {
    u64 d; unsigned xi = __float_as_uint(x);
    asm("mov.b64 %0, {%1, %1};" : "=l"(d) : "r"(xi));
    return d;
}
__device__ __forceinline__ float2 un2(u64 v) {
    float2 r;
    asm("mov.b64 {%0, %1}, %2;" : "=f"(r.x), "=f"(r.y) : "l"(v));
    return r;
}
__device__ __forceinline__ float warp_max(float v) {
    #pragma unroll
    for (int o = 16; o > 0; o >>= 1) v = fmaxf(v, __shfl_xor_sync(0xffffffffu, v, o));
    return v;
}
__device__ __forceinline__ float warp_sum(float v) {
    #pragma unroll
    for (int o = 16; o > 0; o >>= 1) v += __shfl_xor_sync(0xffffffffu, v, o);
    return v;
}
__device__ __forceinline__ void cp_async16(uint32_t saddr, const void* gptr) {
    asm volatile("cp.async.cg.shared.global [%0], [%1], 16;" :: "r"(saddr), "l"(gptr));
}
__device__ __forceinline__ uint32_t to_tf32(float f) {
    uint32_t u;
    asm("cvt.rna.tf32.f32 %0, %1;" : "=r"(u) : "f"(f));
    return u;
}

// ---------------- tf32 mma.sync GEMM tile (3-stage pipeline) ------------------
__device__ __forceinline__ void gemm_mma_tile(
    const float* __restrict__ X, const float* __restrict__ W,
    float* __restrict__ Y, int ldY, int ocol0, int k0,
    float (*xs)[NB * XSTR], float (*ws)[GOB * WSTR])
{
    int t = threadIdx.x, warp = t >> 5, lane = t & 31;
    int qr = lane >> 2, qc = lane & 3;

    float c[2][2][4];
    #pragma unroll
    for (int mt = 0; mt < 2; mt++)
        #pragma unroll
        for (int nt = 0; nt < 2; nt++)
            #pragma unroll
            for (int i = 0; i < 4; i++) c[mt][nt][i] = 0.f;

    uint32_t xsa[3], wsa[3];
    #pragma unroll
    for (int i = 0; i < 3; i++) {
        xsa[i] = (uint32_t)__cvta_generic_to_shared(xs[i]);
        wsa[i] = (uint32_t)__cvta_generic_to_shared(ws[i]);
    }

    #define GLOAD(s_) do {                                                        \
        int buf = (s_) % 3;                                                       \
        int kk = k0 + (s_) * GKS;                                                 \
        _Pragma("unroll")                                                         \
        for (int it = 0; it < 2; it++) {                                          \
            int idx = it * 128 + t; int row = idx >> 3, c4 = idx & 7;             \
            cp_async16(xsa[buf] + (uint32_t)(row * XSTR + c4 * 4) * 4,            \
                       X + (size_t)row * HID + kk + c4 * 4);                      \
        }                                                                         \
        _Pragma("unroll")                                                         \
        for (int it = 0; it < 4; it++) {                                          \
            int idx = it * 128 + t; int row = idx >> 3, c4 = idx & 7;             \
            cp_async16(wsa[buf] + (uint32_t)(row * WSTR + c4 * 4) * 4,            \
                       W + (size_t)row * HID + kk + c4 * 4);                      \
        }                                                                         \
        asm volatile("cp.async.commit_group;" ::: "memory");                      \
    } while (0)

    GLOAD(0);
    GLOAD(1);
    for (int s = 0; s < GNSTG; s++) {
        if (s + 2 < GNSTG) {
            GLOAD(s + 2);
            asm volatile("cp.async.wait_group 2;" ::: "memory");
        } else if (s + 1 < GNSTG) {
            asm volatile("cp.async.wait_group 1;" ::: "memory");
        } else {
            asm volatile("cp.async.wait_group 0;" ::: "memory");
        }
        __syncthreads();
        const float* xb = xs[s % 3];
        const float* wb = ws[s % 3];
        #pragma unroll
        for (int ks = 0; ks < 4; ks++) {
            int kc = ks * 8;
            uint32_t A[2][4], B[2][2];
            #pragma unroll
            for (int mt = 0; mt < 2; mt++) {
                int r0 = mt * 16 + qr;
                A[mt][0] = to_tf32(xb[(r0)     * XSTR + kc + qc]);
                A[mt][1] = to_tf32(xb[(r0 + 8) * XSTR + kc + qc]);
                A[mt][2] = to_tf32(xb[(r0)     * XSTR + kc + qc + 4]);
                A[mt][3] = to_tf32(xb[(r0 + 8) * XSTR + kc + qc + 4]);
            }
            #pragma unroll
            for (int nt = 0; nt < 2; nt++) {
                int o = warp * 16 + nt * 8 + qr;
                B[nt][0] = to_tf32(wb[o * WSTR + kc + qc]);
                B[nt][1] = to_tf32(wb[o * WSTR + kc + qc + 4]);
            }
            #pragma unroll
            for (int mt = 0; mt < 2; mt++)
                #pragma unroll
                for (int nt = 0; nt < 2; nt++)
                    asm volatile(
                        "mma.sync.aligned.m16n8k8.row.col.f32.tf32.tf32.f32 "
                        "{%0,%1,%2,%3}, {%4,%5,%6,%7}, {%8,%9}, {%0,%1,%2,%3};"
                        : "+f"(c[mt][nt][0]), "+f"(c[mt][nt][1]),
                          "+f"(c[mt][nt][2]), "+f"(c[mt][nt][3])
                        : "r"(A[mt][0]), "r"(A[mt][1]), "r"(A[mt][2]), "r"(A[mt][3]),
                          "r"(B[nt][0]), "r"(B[nt][1]));
        }
        __syncthreads();
    }
    #undef GLOAD

    #pragma unroll
    for (int mt = 0; mt < 2; mt++)
        #pragma unroll
        for (int nt = 0; nt < 2; nt++) {
            int o = ocol0 + warp * 16 + nt * 8 + qc * 2;
            int b0 = mt * 16 + qr;
            *(float2*)(&Y[(size_t)b0 * ldY + o])       = make_float2(c[mt][nt][0], c[mt][nt][1]);
            *(float2*)(&Y[(size_t)(b0 + 8) * ldY + o]) = make_float2(c[mt][nt][2], c[mt][nt][3]);
        }
}

__global__ __launch_bounds__(128) void gemm_qkv_kernel(
    const float* __restrict__ X, const float* __restrict__ Wq,
    const float* __restrict__ Wk, const float* __restrict__ Wv)
{
    __shared__ __align__(16) float xs[3][NB * XSTR];
    __shared__ __align__(16) float ws[3][GOB * WSTR];
    int o0 = blockIdx.x * GOB;
    int sp = blockIdx.y;
    const float* W;
    if (o0 < OQ)            W = Wq + (size_t)o0 * HID;
    else if (o0 < OQ + OKV) W = Wk + (size_t)(o0 - OQ) * HID;
    else                    W = Wv + (size_t)(o0 - OQ - OKV) * HID;
    gemm_mma_tile(X, W, g_qkv_part[sp], OQKV, o0, sp * KS, xs, ws);
}

__global__ __launch_bounds__(128) void gemm_wo_kernel(const float* __restrict__ Wo)
{
    __shared__ __align__(16) float xs[3][NB * XSTR];
    __shared__ __align__(16) float ws[3][GOB * WSTR];
    int o0 = blockIdx.x * GOB;
    int sp = blockIdx.y;
    gemm_mma_tile(g_ctx, Wo + (size_t)o0 * HID, g_out_part[sp], HID, o0, sp * KS, xs, ws);
}

// -------- reduce split-K partials + RoPE (q,k) / identity (v) ----------------
__global__ __launch_bounds__(128) void reduce_rope_kernel(
    const int* __restrict__ pos, const float* __restrict__ cosc,
    const float* __restrict__ sinc)
{
    int u = blockIdx.x % 48;
    int b = blockIdx.x / 48;
    int t = threadIdx.x;
    size_t base = (size_t)b * OQKV + u * 128;
    if (u < 40) {
        if (t < 64) {
            float x1 = 0.f, x2 = 0.f;
            #pragma unroll
            for (int s = 0; s < SPLITK; s++) {
                x1 += g_qkv_part[s][base + t];
                x2 += g_qkv_part[s][base + t + 64];
            }
            int p = pos[b];
            float c = cosc[p * 64 + t], sn = sinc[p * 64 + t];
            g_qkv[base + t]      = x1 * c - x2 * sn;
            g_qkv[base + t + 64] = x2 * c + x1 * sn;
        }
    } else {
        float x = 0.f;
        #pragma unroll
        for (int s = 0; s < SPLITK; s++) x += g_qkv_part[s][base + t];
        g_qkv[base + t] = x;
    }
}

__global__ __launch_bounds__(128) void reduce_out_kernel(float* __restrict__ out)
{
    int i = (blockIdx.x * 128 + threadIdx.x) * 4;
    float4 acc = make_float4(0.f, 0.f, 0.f, 0.f);
    #pragma unroll
    for (int s = 0; s < SPLITK; s++) {
        float4 v = *(const float4*)(&g_out_part[s][i]);
        acc.x += v.x; acc.y += v.y; acc.z += v.z; acc.w += v.w;
    }
    *(float4*)(&out[i]) = acc;
}

// ---------------- fused flash-decode split + KV-cache copy -------------------
__global__ __launch_bounds__(128) void attn_kernel(
    const float* __restrict__ pk, const float* __restrict__ pv,
    const float* __restrict__ bias, float* __restrict__ out_k,
    float* __restrict__ out_v)
{
    extern __shared__ __align__(16) float smem[];
    float* qs = smem;
    float* sbias = smem + NG*DHD;
    float* bufK[2] = { smem + NG*DHD + CHUNK, smem + NG*DHD + CHUNK + TILE_KF };
    float* bufV[2] = { smem + NG*DHD + CHUNK + 2*TILE_KF,
                       smem + NG*DHD + CHUNK + 2*TILE_KF + TILE_VF };

    int split = blockIdx.x, h = blockIdx.y, b = blockIdx.z;
    int t = threadIdx.x, warp = t >> 5, lane = t & 31;

    const float* kbase = pk + (size_t)(b * NHKV + h) * PAST * DHD;
    const float* vbase = pv + (size_t)(b * NHKV + h) * PAST * DHD;
    float* okbase = out_k + (size_t)(b * NHKV + h) * TTOT * DHD;
    float* ovbase = out_v + (size_t)(b * NHKV + h) * TTOT * DHD;

    uint32_t sm0 = (uint32_t)__cvta_generic_to_shared(smem);
    uint32_t kOff[2] = { sm0 + (uint32_t)(NG*DHD + CHUNK)*4,
                         sm0 + (uint32_t)(NG*DHD + CHUNK + TILE_KF)*4 };
    uint32_t vOff[2] = { sm0 + (uint32_t)(NG*DHD + CHUNK + 2*TILE_KF)*4,
                         sm0 + (uint32_t)(NG*DHD + CHUNK + 2*TILE_KF + TILE_VF)*4 };

    int tstart = split * CHUNK;

    {
        #pragma unroll
        for (int it = 0; it < 8; it++) {
            int idx = it * 128 + t;
            int rr = idx >> 5, c4 = idx & 31;
            size_t go = (size_t)(tstart + rr) * DHD + c4 * 4;
            cp_async16(kOff[0] + (uint32_t)(rr * KPAD + c4 * 4) * 4, kbase + go);
            cp_async16(vOff[0] + (uint32_t)(rr * DHD  + c4 * 4) * 4, vbase + go);
        }
        asm volatile("cp.async.commit_group;" ::: "memory");
    }

    for (int i = t; i < NG * DHD; i += 128)
        qs[i] = g_qkv[(size_t)b * OQKV + (h * NG + (i >> 7)) * DHD + (i & 127)];
    #pragma unroll
    for (int i = 0; i < CHUNK / 128; i++)
        sbias[i * 128 + t] = bias[(size_t)b * TTOT + tstart + i * 128 + t];

    float m = -INFINITY, l = 0.f;
    u64 a01 = 0ull, a23 = 0ull;

    for (int ti = 0; ti < NT; ti++) {
        int t0 = tstart + ti * KTILE;
        int cur = ti & 1;
        if (ti + 1 < NT) {
            int nxt = cur ^ 1;
            int t1 = t0 + KTILE;
            #pragma unroll
            for (int it = 0; it < 8; it++) {
                int idx = it * 128 + t;
                int rr = idx >> 5, c4 = idx & 31;
                size_t go = (size_t)(t1 + rr) * DHD + c4 * 4;
                cp_async16(kOff[nxt] + (uint32_t)(rr * KPAD + c4 * 4) * 4, kbase + go);
                cp_async16(vOff[nxt] + (uint32_t)(rr * DHD  + c4 * 4) * 4, vbase + go);
            }
            asm volatile("cp.async.commit_group;" ::: "memory");
            asm volatile("cp.async.wait_group 1;" ::: "memory");
        } else {
            asm volatile("cp.async.wait_group 0;" ::: "memory");
        }
        __syncthreads();

        const float* kb = bufK[cur];
        const float* vb = bufV[cur];

        if (t == 0) {
            asm volatile("fence.proxy.async.shared::cta;" ::: "memory");
            asm volatile("cp.async.bulk.global.shared::cta.bulk_group [%0], [%1], %2;"
                         :: "l"(ovbase + (size_t)t0 * DHD), "r"(vOff[cur]),
                            "r"((int)(TILE_VF * 4)) : "memory");
            asm volatile("cp.async.bulk.commit_group;" ::: "memory");
        }

        const float* qg = qs + warp * DHD;
        u64 s01 = 0ull, s23 = 0ull;
        #pragma unroll
        for (int d4 = 0; d4 < 32; d4++) {
            ulonglong2 qv = *(const ulonglong2*)(qg + d4 * 4);
            ulonglong2 kv = *(const ulonglong2*)(kb + (size_t)lane * KPAD + d4 * 4);
            s01 = fma2(qv.x, kv.x, s01);
            s23 = fma2(qv.y, kv.y, s23);
        }
        float2 sa = un2(s01), sb = un2(s23);
        float s = ((sa.x + sa.y) + (sb.x + sb.y)) * ATT_SCALE + sbias[ti * KTILE + lane];

        float mt = warp_max(s);
        float mnew = fmaxf(m, mt);
        float alpha = __expf(m - mnew);
        float p = __expf(s - mnew);
        l = l * alpha + warp_sum(p);
        m = mnew;
        u64 al2 = dup2(alpha);
        a01 = fma2(a01, al2, 0ull);
        a23 = fma2(a23, al2, 0ull);
        #pragma unroll
        for (int j = 0; j < KTILE; j++) {
            float pj = __shfl_sync(0xffffffffu, p, j);
            u64 pj2 = dup2(pj);
            ulonglong2 vv = *(const ulonglong2*)(vb + j * DHD + lane * 4);
            a01 = fma2(pj2, vv.x, a01);
            a23 = fma2(pj2, vv.y, a23);
        }

        #pragma unroll
        for (int it = 0; it < 8; it++) {
            int idx = it * 128 + t;
            int rr = idx >> 5, c4 = idx & 31;
            __stcs((float4*)(okbase + (size_t)(t0 + rr) * DHD + c4 * 4),
                   *(const float4*)(kb + rr * KPAD + c4 * 4));
        }

        if (t == 0)
            asm volatile("cp.async.bulk.wait_group.read 0;" ::: "memory");
        __syncthreads();
    }

    float2 f0 = un2(a01), f1 = un2(a23);
    float4 a = make_float4(f0.x, f0.y, f1.x, f1.y);

    if (split == NSPLIT - 1) {
        const float* kn = &g_qkv[(size_t)b * OQKV + OQ + h * DHD];
        const float* vn = &g_qkv[(size_t)b * OQKV + OQ + OKV + h * DHD];
        if (t < 32)      *(float4*)(okbase + (size_t)PAST * DHD + t * 4) = *(const float4*)(kn + t * 4);
        else if (t < 64) *(float4*)(ovbase + (size_t)PAST * DHD + (t - 32) * 4) = *(const float4*)(vn + (t - 32) * 4);
        float sp = 0.f;
        #pragma unroll
        for (int i = lane; i < DHD; i += 32) sp += qs[warp * DHD + i] * kn[i];
        sp = warp_sum(sp) * ATT_SCALE + bias[(size_t)b * TTOT + PAST];
        float mnew = fmaxf(m, sp);
        float alpha = __expf(m - mnew);
        float p = __expf(sp - mnew);
        l = l * alpha + p;
        m = mnew;
        float4 vv = *(const float4*)(vn + lane * 4);
        a.x = a.x * alpha + p * vv.x; a.y = a.y * alpha + p * vv.y;
        a.z = a.z * alpha + p * vv.z; a.w = a.w * alpha + p * vv.w;
    }

    int pidx = ((b * NHKV + h) * NG + warp) * NSPLIT + split;
    if (lane == 0) { g_pm[pidx] = m; g_pl[pidx] = l; }
    *(float4*)(&g_pacc[(size_t)pidx * DHD + lane * 4]) = a;

    if (t == 0)
        asm volatile("cp.async.bulk.wait_group 0;" ::: "memory");
}

// ---------------- combine split partials -> context --------------------------
__global__ __launch_bounds__(128) void combine_kernel()
{
    int bh = blockIdx.x;
    int b = bh / NHQ, hq = bh % NHQ;
    int h = hq / NG, g = hq % NG;
    int pbase = ((b * NHKV + h) * NG + g) * NSPLIT;
    int d = threadIdx.x;

    float M = -INFINITY;
    #pragma unroll
    for (int s = 0; s < NSPLIT; s++) M = fmaxf(M, g_pm[pbase + s]);
    float L0 = 0.f, L1 = 0.f, c0 = 0.f, c1 = 0.f;
    #pragma unroll
    for (int s = 0; s < NSPLIT; s += 2) {
        float w0 = __expf(g_pm[pbase + s]     - M);
        float w1 = __expf(g_pm[pbase + s + 1] - M);
        L0 += w0 * g_pl[pbase + s];
        L1 += w1 * g_pl[pbase + s + 1];
        c0 += w0 * g_pacc[(size_t)(pbase + s)     * DHD + d];
        c1 += w1 * g_pacc[(size_t)(pbase + s + 1) * DHD + d];
    }
    g_ctx[(size_t)bh * DHD + d] = (c0 + c1) / (L0 + L1);
}

// ---------------- launch ----------------------------------------------------
extern "C" void kernel_launch(void* const* d_in, const int* in_sizes, int n_in,
                              void* d_out, int out_size)
{
    const float* hidden = (const float*)d_in[0];
    const float* bias   = (const float*)d_in[1];
    const int*   pos    = (const int*)d_in[2];
    const float* cosc   = (const float*)d_in[3];
    const float* sinc   = (const float*)d_in[4];
    const float* pk     = (const float*)d_in[5];
    const float* pv     = (const float*)d_in[6];
    const float* Wq     = (const float*)d_in[7];
    const float* Wk     = (const float*)d_in[8];
    const float* Wv     = (const float*)d_in[9];
    const float* Wo     = (const float*)d_in[10];

    float* out = (float*)d_out;
    size_t kv_elems = (size_t)NB * NHKV * TTOT * DHD;
    float* out_k = out + (size_t)NB * HID;
    float* out_v = out_k + kv_elems;

    static bool attr_set = false;
    if (!attr_set) {
        cudaFuncSetAttribute(attn_kernel, cudaFuncAttributeMaxDynamicSharedMemorySize,
                             ATTN_SMEM_BYTES);
        attr_set = true;
    }

    gemm_qkv_kernel<<<dim3(OQKV / GOB, SPLITK), 128>>>(hidden, Wq, Wk, Wv);
    reduce_rope_kernel<<<NB * 48, 128>>>(pos, cosc, sinc);
    attn_kernel<<<dim3(NSPLIT, NHKV, NB), 128, ATTN_SMEM_BYTES>>>(pk, pv, bias, out_k, out_v);
    combine_kernel<<<NB * NHQ, 128>>>();
    gemm_wo_kernel<<<dim3(HID / GOB, SPLITK), 128>>>(Wo);
    reduce_out_kernel<<<NB * HID / 512, 128>>>(out);
}